// round 3
// baseline (speedup 1.0000x reference)
#include <cuda_runtime.h>
#include <cstdint>

#define BB 4
#define NN 1024
#define CC 1024
#define HH 16
#define HDIM 64

// ---------------- scratch ----------------
static constexpr size_t OFF_Q   = 0;
static constexpr size_t OFF_K   = OFF_Q + (size_t)BB*HH*NN*HDIM;
static constexpr size_t OFF_VT  = OFF_K + (size_t)BB*HH*NN*HDIM;
static constexpr size_t OFF_MID = OFF_VT + (size_t)BB*HH*NN*HDIM;
static constexpr size_t OFF_INV = OFF_MID + (size_t)BB*NN*CC;
static constexpr size_t OFF_S   = OFF_INV + (size_t)BB*HH*NN;
static constexpr size_t SCRATCH_TOTAL = OFF_S + (size_t)BB*HH*NN*NN;
__device__ float g_scratch[SCRATCH_TOTAL];

// fp32 -> tf32 round-to-nearest-even
__device__ __forceinline__ uint32_t f2tf32(float x) {
  uint32_t u = __float_as_uint(x);
  u = (u + 0xFFFu + ((u >> 13) & 1u)) & 0xFFFFE000u;
  return u;
}

__device__ __forceinline__ void mma_tf32(float* c, const uint32_t* a, uint32_t b0, uint32_t b1) {
  asm volatile(
      "mma.sync.aligned.m16n8k8.row.col.f32.tf32.tf32.f32 "
      "{%0,%1,%2,%3}, {%4,%5,%6,%7}, {%8,%9}, {%0,%1,%2,%3};"
      : "+f"(c[0]), "+f"(c[1]), "+f"(c[2]), "+f"(c[3])
      : "r"(a[0]), "r"(a[1]), "r"(a[2]), "r"(a[3]), "r"(b0), "r"(b1));
}

// ---------------- warp-mma tf32 GEMM ----------------
// C[128-tile rows, NT cols] = A[rows,K] @ B[cols,K]^T, fp32 gmem (K-major both).
// EPI: 0 plain->O0, 1 qkv scatter, 2 AV->mid, 3 proj+bias->O0
template <int NT, int EPI>
__global__ __launch_bounds__(256) void wm_gemm(
    const float* __restrict__ Ag, const float* __restrict__ Bg,
    int lda, int ldb, int K, size_t batchA, size_t batchB,
    const float* __restrict__ bias,
    float* __restrict__ O0, float* __restrict__ O1, float* __restrict__ O2,
    int ldo, size_t batchO) {
  constexpr int SSTR = 36;               // floats per smem row (32 + pad 4)
  constexpr int NBI = NT / 32;           // B prefetch float4s per thread
  constexpr int NFRAG = NT / 16;         // n-fragments per warp (warp covers NT/2)
  __shared__ float As[128 * SSTR];
  __shared__ float Bs[NT * SSTR];

  const int tid = threadIdx.x;
  const int lane = tid & 31, wid = tid >> 5;
  const int wm = (wid & 3) * 32;
  const int wn = (wid >> 2) * (NT / 2);
  const int g = lane >> 2, t = lane & 3;
  const int rb = blockIdx.y * 128;
  const int ob = blockIdx.x * NT;
  const int z = blockIdx.z;
  const float* Ab = Ag + (size_t)z * batchA;
  const float* Bb = Bg + (size_t)z * batchB;

  const int lm = tid >> 3;               // load row 0..31 step (of 128 via +32*i? no: idx>>3)
  (void)lm;

  float acc[2][NFRAG][4];
#pragma unroll
  for (int mi = 0; mi < 2; mi++)
#pragma unroll
    for (int ni = 0; ni < NFRAG; ni++)
#pragma unroll
      for (int j = 0; j < 4; j++) acc[mi][ni][j] = 0.f;

  float4 pa[4], pb[NBI];
  const int KT = K >> 5;

  // prefetch tile 0
#pragma unroll
  for (int i = 0; i < 4; i++) {
    int idx = tid + i * 256, m = idx >> 3, kq = (idx & 7) << 2;
    pa[i] = __ldg((const float4*)(Ab + (size_t)(rb + m) * lda + kq));
  }
#pragma unroll
  for (int i = 0; i < NBI; i++) {
    int idx = tid + i * 256, m = idx >> 3, kq = (idx & 7) << 2;
    pb[i] = __ldg((const float4*)(Bb + (size_t)(ob + m) * ldb + kq));
  }
  // store tile 0
#pragma unroll
  for (int i = 0; i < 4; i++) {
    int idx = tid + i * 256, m = idx >> 3, kq = (idx & 7) << 2;
    uint4 u = make_uint4(f2tf32(pa[i].x), f2tf32(pa[i].y), f2tf32(pa[i].z), f2tf32(pa[i].w));
    *(uint4*)&As[m * SSTR + kq] = u;
  }
#pragma unroll
  for (int i = 0; i < NBI; i++) {
    int idx = tid + i * 256, m = idx >> 3, kq = (idx & 7) << 2;
    uint4 u = make_uint4(f2tf32(pb[i].x), f2tf32(pb[i].y), f2tf32(pb[i].z), f2tf32(pb[i].w));
    *(uint4*)&Bs[m * SSTR + kq] = u;
  }
  __syncthreads();

  for (int kt = 0; kt < KT; kt++) {
    // prefetch next tile
    if (kt + 1 < KT) {
      const int k0g = (kt + 1) << 5;
#pragma unroll
      for (int i = 0; i < 4; i++) {
        int idx = tid + i * 256, m = idx >> 3, kq = (idx & 7) << 2;
        pa[i] = __ldg((const float4*)(Ab + (size_t)(rb + m) * lda + k0g + kq));
      }
#pragma unroll
      for (int i = 0; i < NBI; i++) {
        int idx = tid + i * 256, m = idx >> 3, kq = (idx & 7) << 2;
        pb[i] = __ldg((const float4*)(Bb + (size_t)(ob + m) * ldb + k0g + kq));
      }
    }
    // MMA over current smem tile
#pragma unroll
    for (int ks = 0; ks < 4; ks++) {
      const int k0 = ks * 8;
      uint32_t a[2][4];
#pragma unroll
      for (int mi = 0; mi < 2; mi++) {
        const int r = wm + mi * 16;
        a[mi][0] = __float_as_uint(As[(r + g) * SSTR + k0 + t]);
        a[mi][1] = __float_as_uint(As[(r + g + 8) * SSTR + k0 + t]);
        a[mi][2] = __float_as_uint(As[(r + g) * SSTR + k0 + t + 4]);
        a[mi][3] = __float_as_uint(As[(r + g + 8) * SSTR + k0 + t + 4]);
      }
#pragma unroll
      for (int ni = 0; ni < NFRAG; ni++) {
        uint32_t b0 = __float_as_uint(Bs[(wn + ni * 8 + g) * SSTR + k0 + t]);
        uint32_t b1 = __float_as_uint(Bs[(wn + ni * 8 + g) * SSTR + k0 + t + 4]);
        mma_tf32(acc[0][ni], a[0], b0, b1);
        mma_tf32(acc[1][ni], a[1], b0, b1);
      }
    }
    __syncthreads();
    if (kt + 1 < KT) {
#pragma unroll
      for (int i = 0; i < 4; i++) {
        int idx = tid + i * 256, m = idx >> 3, kq = (idx & 7) << 2;
        uint4 u = make_uint4(f2tf32(pa[i].x), f2tf32(pa[i].y), f2tf32(pa[i].z), f2tf32(pa[i].w));
        *(uint4*)&As[m * SSTR + kq] = u;
      }
#pragma unroll
      for (int i = 0; i < NBI; i++) {
        int idx = tid + i * 256, m = idx >> 3, kq = (idx & 7) << 2;
        uint4 u = make_uint4(f2tf32(pb[i].x), f2tf32(pb[i].y), f2tf32(pb[i].z), f2tf32(pb[i].w));
        *(uint4*)&Bs[m * SSTR + kq] = u;
      }
      __syncthreads();
    }
  }

  // ---- epilogue: lane holds C[row g,g+8][col 2t,2t+1] per frag ----
#pragma unroll
  for (int mi = 0; mi < 2; mi++) {
#pragma unroll
    for (int ni = 0; ni < NFRAG; ni++) {
      const int row0 = rb + wm + mi * 16 + g;
      const int row1 = row0 + 8;
      const int col = ob + wn + ni * 8 + 2 * t;
      const float c0 = acc[mi][ni][0], c1 = acc[mi][ni][1];
      const float c2 = acc[mi][ni][2], c3 = acc[mi][ni][3];
      if (EPI == 0) {
        float* d0 = O0 + (size_t)z * batchO + (size_t)row0 * ldo + col;
        float* d1 = O0 + (size_t)z * batchO + (size_t)row1 * ldo + col;
        *(float2*)d0 = make_float2(c0, c1);
        *(float2*)d1 = make_float2(c2, c3);
      } else if (EPI == 1) {
        const int which = col >> 10, h = (col >> 6) & 15, d0i = col & 63;
        const float b0v = __ldg(bias + col), b1v = __ldg(bias + col + 1);
        const int r0 = row0, r1 = row1;
        const int b0b = r0 >> 10, n0 = r0 & 1023;
        const int b1b = r1 >> 10, n1 = r1 & 1023;
        if (which == 2) {
          size_t base0 = ((((size_t)b0b * HH + h) * HDIM) + d0i) * NN + n0;
          size_t base1 = ((((size_t)b1b * HH + h) * HDIM) + d0i) * NN + n1;
          O2[base0] = c0 + b0v; O2[base0 + NN] = c1 + b1v;
          O2[base1] = c2 + b0v; O2[base1 + NN] = c3 + b1v;
        } else {
          float* dst = (which == 0) ? O0 : O1;
          const float sc = (which == 0) ? 0.125f : 1.0f;
          float* p0 = dst + ((((size_t)b0b * HH + h) * NN) + n0) * HDIM + d0i;
          float* p1 = dst + ((((size_t)b1b * HH + h) * NN) + n1) * HDIM + d0i;
          *(float2*)p0 = make_float2((c0 + b0v) * sc, (c1 + b1v) * sc);
          *(float2*)p1 = make_float2((c2 + b0v) * sc, (c3 + b1v) * sc);
        }
      } else if (EPI == 2) {
        const int bb = z >> 4, gh = z & 15;
        float* p0 = O0 + ((size_t)bb * NN + row0) * CC + gh * HDIM + col;
        float* p1 = O0 + ((size_t)bb * NN + row1) * CC + gh * HDIM + col;
        *(float2*)p0 = make_float2(c0, c1);
        *(float2*)p1 = make_float2(c2, c3);
      } else {
        const float b0v = __ldg(bias + col), b1v = __ldg(bias + col + 1);
        float* p0 = O0 + (size_t)row0 * ldo + col;
        float* p1 = O0 + (size_t)row1 * ldo + col;
        *(float2*)p0 = make_float2(c0 + b0v, c1 + b1v);
        *(float2*)p1 = make_float2(c2 + b0v, c3 + b1v);
      }
    }
  }
}

// ---------------- mix1: t[b,g,n,m] = sum_h wl[g,h] s[b,h,n,m] + bl[g] ----------------
__global__ __launch_bounds__(256) void mix1_kernel(
    const float* __restrict__ wl, const float* __restrict__ bl,
    const float* __restrict__ s, float* __restrict__ attn) {
  __shared__ float w[256];
  __shared__ float bb[16];
  const int n = blockIdx.x, b = blockIdx.y, tid = threadIdx.x;
  w[tid] = wl[tid];
  if (tid < 16) bb[tid] = bl[tid];
  __syncthreads();
#pragma unroll
  for (int mi = 0; mi < 4; mi++) {
    int m = tid + mi * 256;
    float pv[16];
#pragma unroll
    for (int h = 0; h < 16; h++)
      pv[h] = s[((((size_t)b * 16 + h) << 10) + n) * 1024 + m];
#pragma unroll
    for (int g = 0; g < 16; g++) {
      float a = bb[g];
#pragma unroll
      for (int h = 0; h < 16; h++) a += w[g * 16 + h] * pv[h];
      attn[((((size_t)b * 16 + g) << 10) + n) * 1024 + m] = a;
    }
  }
}

// ---------------- softmax ----------------
__global__ __launch_bounds__(256) void softmax_kernel(float* __restrict__ attn, float* __restrict__ inv) {
  const int warp = threadIdx.x >> 5, lane = threadIdx.x & 31;
  const int row = blockIdx.x * 8 + warp;
  float* p = attn + (size_t)row * 1024;
  float vals[32];
#pragma unroll
  for (int j = 0; j < 8; j++) {
    float4 v = *(const float4*)(p + lane * 4 + 128 * j);
    vals[j * 4 + 0] = v.x; vals[j * 4 + 1] = v.y; vals[j * 4 + 2] = v.z; vals[j * 4 + 3] = v.w;
  }
  float mx = -1e30f;
#pragma unroll
  for (int i = 0; i < 32; i++) mx = fmaxf(mx, vals[i]);
#pragma unroll
  for (int o = 16; o; o >>= 1) mx = fmaxf(mx, __shfl_xor_sync(0xffffffffu, mx, o));
  float sum = 0.f;
#pragma unroll
  for (int i = 0; i < 32; i++) { vals[i] = __expf(vals[i] - mx); sum += vals[i]; }
#pragma unroll
  for (int o = 16; o; o >>= 1) sum += __shfl_xor_sync(0xffffffffu, sum, o);
#pragma unroll
  for (int j = 0; j < 8; j++)
    *(float4*)(p + lane * 4 + 128 * j) =
        make_float4(vals[j * 4 + 0], vals[j * 4 + 1], vals[j * 4 + 2], vals[j * 4 + 3]);
  if (lane == 0) inv[row] = 1.0f / sum;
}

// ---------------- mix2 ----------------
__global__ __launch_bounds__(256) void mix2_kernel(
    const float* __restrict__ ww, const float* __restrict__ bw,
    float* __restrict__ attn, const float* __restrict__ inv) {
  __shared__ float w[256];
  __shared__ float bb[16];
  __shared__ float iv[16];
  const int n = blockIdx.x, b = blockIdx.y, tid = threadIdx.x;
  w[tid] = ww[tid];
  if (tid < 16) {
    bb[tid] = bw[tid];
    iv[tid] = inv[((size_t)b * 16 + tid) * 1024 + n];
  }
  __syncthreads();
#pragma unroll
  for (int mi = 0; mi < 4; mi++) {
    int m = tid + mi * 256;
    float pv[16];
#pragma unroll
    for (int h = 0; h < 16; h++)
      pv[h] = attn[((((size_t)b * 16 + h) << 10) + n) * 1024 + m] * iv[h];
#pragma unroll
    for (int g = 0; g < 16; g++) {
      float a = bb[g];
#pragma unroll
      for (int h = 0; h < 16; h++) a += w[g * 16 + h] * pv[h];
      attn[((((size_t)b * 16 + g) << 10) + n) * 1024 + m] = a;
    }
  }
}

// ---------------- launch ----------------
extern "C" void kernel_launch(void* const* d_in, const int* in_sizes, int n_in,
                              void* d_out, int out_size) {
  const float* x      = (const float*)d_in[0];
  const float* qkv_w  = (const float*)d_in[1];
  const float* qkv_b  = (const float*)d_in[2];
  const float* proj_w = (const float*)d_in[3];
  const float* proj_b = (const float*)d_in[4];
  const float* wl     = (const float*)d_in[5];
  const float* bl     = (const float*)d_in[6];
  const float* ww     = (const float*)d_in[7];
  const float* bw     = (const float*)d_in[8];
  float* out = (float*)d_out;
  float* attn = out + (size_t)BB * NN * CC;

  float* scratch = nullptr;
  cudaGetSymbolAddress((void**)&scratch, g_scratch);
  float* q   = scratch + OFF_Q;
  float* k   = scratch + OFF_K;
  float* vT  = scratch + OFF_VT;
  float* mid = scratch + OFF_MID;
  float* inv = scratch + OFF_INV;
  float* s   = scratch + OFF_S;

  // 1) qkv = x @ qkv_w^T + b -> q(*scale), k, vT
  wm_gemm<128, 1><<<dim3(24, 32, 1), 256>>>(
      x, qkv_w, CC, CC, CC, 0, 0, qkv_b, q, k, vT, 0, 0);
  // 2) s[b,h] = q[b,h] @ k[b,h]^T (64 batches, K=64)
  wm_gemm<128, 0><<<dim3(8, 8, 64), 256>>>(
      q, k, HDIM, HDIM, HDIM, (size_t)NN * HDIM, (size_t)NN * HDIM, nullptr,
      s, nullptr, nullptr, NN, (size_t)NN * NN);
  // 3) pre-softmax talking-heads mix
  mix1_kernel<<<dim3(NN, BB), 256>>>(wl, bl, s, attn);
  // 4) softmax
  softmax_kernel<<<BB * HH * NN / 8, 256>>>(attn, inv);
  // 5) post-softmax talking-heads mix (+normalize)
  mix2_kernel<<<dim3(NN, BB), 256>>>(ww, bw, attn, inv);
  // 6) mid = attn @ vT^T (64 batches, K=1024)
  wm_gemm<64, 2><<<dim3(1, 8, 64), 256>>>(
      attn, vT, NN, NN, NN, (size_t)NN * NN, (size_t)HDIM * NN, nullptr,
      mid, nullptr, nullptr, 0, 0);
  // 7) out = mid @ proj_w^T + proj_b
  wm_gemm<128, 3><<<dim3(8, 32, 1), 256>>>(
      mid, proj_w, CC, CC, CC, 0, 0, proj_b, out, nullptr, nullptr, CC, 0);
}

// round 4
// speedup vs baseline: 2.5889x; 2.5889x over previous
#include <cuda_runtime.h>
#include <cstdint>

#define BB 4
#define NN 1024
#define CC 1024
#define HH 16
#define HDIM 64

typedef unsigned long long ull;

// ---------------- scratch ----------------
static constexpr size_t OFF_Q   = 0;
static constexpr size_t OFF_K   = OFF_Q + (size_t)BB*HH*NN*HDIM;
static constexpr size_t OFF_VT  = OFF_K + (size_t)BB*HH*NN*HDIM;
static constexpr size_t OFF_MID = OFF_VT + (size_t)BB*HH*NN*HDIM;
static constexpr size_t OFF_S   = OFF_MID + (size_t)BB*NN*CC;
static constexpr size_t SCRATCH_TOTAL = OFF_S + (size_t)BB*HH*NN*NN;
__device__ float g_scratch[SCRATCH_TOTAL];

// ---------------- f32x2 helpers ----------------
__device__ __forceinline__ ull splat2(float v) {
  ull r; asm("mov.b64 %0, {%1,%1};" : "=l"(r) : "f"(v)); return r;
}
__device__ __forceinline__ void fma2(ull& d, ull a, ull b) {
  asm("fma.rn.f32x2 %0, %1, %2, %0;" : "+l"(d) : "l"(a), "l"(b));
}
__device__ __forceinline__ float lo32(ull u) { return __uint_as_float((unsigned)u); }
__device__ __forceinline__ float hi32(ull u) { return __uint_as_float((unsigned)(u >> 32)); }

// ---------------- packed-fp32 GEMM ----------------
// C[128 rows, NT cols] = A[rows,K] @ B[cols,K]^T, fp32, K-major both.
// EPI: 0 plain->O0, 1 qkv scatter (q*scale,k,vT,+bias), 2 AV->mid, 3 proj+bias->O0
template <int NT, int EPI>
__global__ __launch_bounds__(256) void g2_gemm(
    const float* __restrict__ Ag, const float* __restrict__ Bg,
    int lda, int ldb, int K, size_t batchA, size_t batchB,
    const float* __restrict__ bias,
    float* __restrict__ O0, float* __restrict__ O1, float* __restrict__ O2,
    int ldo, size_t batchO) {
  constexpr int SROW = 132;          // floats per k-row of smem (pad vs 128)
  constexpr int NCOL = NT / 16;      // cols per thread (8 or 4)
  constexpr int NB = NT / 64;        // B prefetch float4s per thread
  __shared__ float As[16 * SROW];
  __shared__ float Bs[16 * SROW];

  const int tid = threadIdx.x;
  const int ty = tid >> 4, tx = tid & 15;
  const int row0 = ty * 8, col0 = tx * NCOL;
  const int rb = blockIdx.y * 128, ob = blockIdx.x * NT, z = blockIdx.z;
  const float* Ab = Ag + (size_t)z * batchA;
  const float* Bb = Bg + (size_t)z * batchB;

  ull acc[4][NCOL];
#pragma unroll
  for (int mp = 0; mp < 4; mp++)
#pragma unroll
    for (int j = 0; j < NCOL; j++) acc[mp][j] = 0ULL;

  float4 pa[2], pb[NB];
  // load k-tile 0
#pragma unroll
  for (int i = 0; i < 2; i++) {
    int idx = tid + i * 256, r = idx >> 2, kq = (idx & 3) << 2;
    pa[i] = __ldg((const float4*)(Ab + (size_t)(rb + r) * lda + kq));
  }
#pragma unroll
  for (int i = 0; i < NB; i++) {
    int idx = tid + i * 256, r = idx >> 2, kq = (idx & 3) << 2;
    pb[i] = __ldg((const float4*)(Bb + (size_t)(ob + r) * ldb + kq));
  }
#pragma unroll
  for (int i = 0; i < 2; i++) {
    int idx = tid + i * 256, r = idx >> 2, kq = (idx & 3) << 2;
    As[(kq + 0) * SROW + r] = pa[i].x; As[(kq + 1) * SROW + r] = pa[i].y;
    As[(kq + 2) * SROW + r] = pa[i].z; As[(kq + 3) * SROW + r] = pa[i].w;
  }
#pragma unroll
  for (int i = 0; i < NB; i++) {
    int idx = tid + i * 256, r = idx >> 2, kq = (idx & 3) << 2;
    Bs[(kq + 0) * SROW + r] = pb[i].x; Bs[(kq + 1) * SROW + r] = pb[i].y;
    Bs[(kq + 2) * SROW + r] = pb[i].z; Bs[(kq + 3) * SROW + r] = pb[i].w;
  }
  __syncthreads();

  const int KT = K >> 4;
  for (int kt = 0; kt < KT; kt++) {
    if (kt + 1 < KT) {
      const int k0 = (kt + 1) << 4;
#pragma unroll
      for (int i = 0; i < 2; i++) {
        int idx = tid + i * 256, r = idx >> 2, kq = (idx & 3) << 2;
        pa[i] = __ldg((const float4*)(Ab + (size_t)(rb + r) * lda + k0 + kq));
      }
#pragma unroll
      for (int i = 0; i < NB; i++) {
        int idx = tid + i * 256, r = idx >> 2, kq = (idx & 3) << 2;
        pb[i] = __ldg((const float4*)(Bb + (size_t)(ob + r) * ldb + k0 + kq));
      }
    }
#pragma unroll
    for (int kk = 0; kk < 16; kk++) {
      ulonglong2 a01 = *(const ulonglong2*)&As[kk * SROW + row0];
      ulonglong2 a23 = *(const ulonglong2*)&As[kk * SROW + row0 + 4];
      ull ap[4] = {a01.x, a01.y, a23.x, a23.y};
      float bf[NCOL];
#pragma unroll
      for (int j4 = 0; j4 < NCOL; j4 += 4)
        *(float4*)&bf[j4] = *(const float4*)&Bs[kk * SROW + col0 + j4];
#pragma unroll
      for (int j = 0; j < NCOL; j++) {
        ull bsp = splat2(bf[j]);
#pragma unroll
        for (int mp = 0; mp < 4; mp++) fma2(acc[mp][j], ap[mp], bsp);
      }
    }
    __syncthreads();
    if (kt + 1 < KT) {
#pragma unroll
      for (int i = 0; i < 2; i++) {
        int idx = tid + i * 256, r = idx >> 2, kq = (idx & 3) << 2;
        As[(kq + 0) * SROW + r] = pa[i].x; As[(kq + 1) * SROW + r] = pa[i].y;
        As[(kq + 2) * SROW + r] = pa[i].z; As[(kq + 3) * SROW + r] = pa[i].w;
      }
#pragma unroll
      for (int i = 0; i < NB; i++) {
        int idx = tid + i * 256, r = idx >> 2, kq = (idx & 3) << 2;
        Bs[(kq + 0) * SROW + r] = pb[i].x; Bs[(kq + 1) * SROW + r] = pb[i].y;
        Bs[(kq + 2) * SROW + r] = pb[i].z; Bs[(kq + 3) * SROW + r] = pb[i].w;
      }
      __syncthreads();
    }
  }

  // ---- epilogue: acc[mp][j] packs rows (row0+2mp, +1) ----
  float biasv[NCOL];
  if (EPI == 1 || EPI == 3) {
#pragma unroll
    for (int j4 = 0; j4 < NCOL; j4 += 4)
      *(float4*)&biasv[j4] = __ldg((const float4*)(bias + ob + col0 + j4));
  }
#pragma unroll
  for (int mp = 0; mp < 4; mp++) {
    const int r0 = rb + row0 + 2 * mp;
    float lo[NCOL], hi[NCOL];
#pragma unroll
    for (int j = 0; j < NCOL; j++) { lo[j] = lo32(acc[mp][j]); hi[j] = hi32(acc[mp][j]); }
    if (EPI == 0) {
      float* p0 = O0 + (size_t)z * batchO + (size_t)r0 * ldo + ob + col0;
      float* p1 = p0 + ldo;
#pragma unroll
      for (int j4 = 0; j4 < NCOL; j4 += 4) {
        *(float4*)(p0 + j4) = make_float4(lo[j4], lo[j4 + 1], lo[j4 + 2], lo[j4 + 3]);
        *(float4*)(p1 + j4) = make_float4(hi[j4], hi[j4 + 1], hi[j4 + 2], hi[j4 + 3]);
      }
    } else if (EPI == 1) {
      const int o0 = ob + col0;
      const int which = o0 >> 10, h = (o0 >> 6) & 15, d0 = o0 & 63;
      const int bcb = r0 >> 10, n0 = r0 & 1023;
      if (which == 2) {
#pragma unroll
        for (int j = 0; j < NCOL; j++) {
          float bv = biasv[j];
          *(float2*)(O2 + ((((size_t)bcb * HH + h) * HDIM + d0 + j) << 10) + n0) =
              make_float2(lo[j] + bv, hi[j] + bv);
        }
      } else {
        float* dst = (which == 0) ? O0 : O1;
        const float sc = (which == 0) ? 0.125f : 1.0f;
        float* p0 = dst + (((size_t)bcb * HH + h) * NN + n0) * HDIM + d0;
        float* p1 = p0 + HDIM;
#pragma unroll
        for (int j4 = 0; j4 < NCOL; j4 += 4) {
          *(float4*)(p0 + j4) = make_float4((lo[j4] + biasv[j4]) * sc, (lo[j4 + 1] + biasv[j4 + 1]) * sc,
                                            (lo[j4 + 2] + biasv[j4 + 2]) * sc, (lo[j4 + 3] + biasv[j4 + 3]) * sc);
          *(float4*)(p1 + j4) = make_float4((hi[j4] + biasv[j4]) * sc, (hi[j4 + 1] + biasv[j4 + 1]) * sc,
                                            (hi[j4 + 2] + biasv[j4 + 2]) * sc, (hi[j4 + 3] + biasv[j4 + 3]) * sc);
        }
      }
    } else if (EPI == 2) {
      const int bcb = z >> 4, g = z & 15;
      float* p0 = O0 + ((size_t)bcb * NN + r0) * CC + g * HDIM + ob + col0;
      float* p1 = p0 + CC;
#pragma unroll
      for (int j4 = 0; j4 < NCOL; j4 += 4) {
        *(float4*)(p0 + j4) = make_float4(lo[j4], lo[j4 + 1], lo[j4 + 2], lo[j4 + 3]);
        *(float4*)(p1 + j4) = make_float4(hi[j4], hi[j4 + 1], hi[j4 + 2], hi[j4 + 3]);
      }
    } else {
      float* p0 = O0 + (size_t)r0 * ldo + ob + col0;
      float* p1 = p0 + ldo;
#pragma unroll
      for (int j4 = 0; j4 < NCOL; j4 += 4) {
        *(float4*)(p0 + j4) = make_float4(lo[j4] + biasv[j4], lo[j4 + 1] + biasv[j4 + 1],
                                          lo[j4 + 2] + biasv[j4 + 2], lo[j4 + 3] + biasv[j4 + 3]);
        *(float4*)(p1 + j4) = make_float4(hi[j4] + biasv[j4], hi[j4 + 1] + biasv[j4 + 1],
                                          hi[j4 + 2] + biasv[j4 + 2], hi[j4 + 3] + biasv[j4 + 3]);
      }
    }
  }
}

// ---------------- fused mix1 + softmax + mix2 ----------------
// CTA per (n, b). smem T[16][1024] holds logits/exp; attn written once.
__global__ __launch_bounds__(256) void fused_mix_softmax(
    const float* __restrict__ wl, const float* __restrict__ bl,
    const float* __restrict__ ww, const float* __restrict__ bw,
    const float* __restrict__ s, float* __restrict__ attn) {
  extern __shared__ float sm[];
  float* T = sm;                     // 16*1024
  float* wls  = sm + 16 * 1024;      // 256
  float* wwi  = wls + 256;           // 256
  float* bls  = wwi + 256;           // 16
  float* bws  = bls + 16;            // 16
  float* invs = bws + 16;            // 16
  const int n = blockIdx.x, b = blockIdx.y, tid = threadIdx.x;
  const int lane = tid & 31;
  wls[tid] = wl[tid];
  if (tid < 16) bls[tid] = bl[tid];
  __syncthreads();

  // phase 1: T[g][m] = sum_h wl[g,h] * s[b,h,n,m] + bl[g]
  const float* sb = s + (size_t)b * 16 * 1048576 + (size_t)n * 1024;
#pragma unroll
  for (int half = 0; half < 2; half++) {
    const int m = tid * 2 + half * 512;
    float2 sv[16];
#pragma unroll
    for (int h = 0; h < 16; h++) sv[h] = *(const float2*)(sb + (size_t)h * 1048576 + m);
#pragma unroll
    for (int g = 0; g < 16; g++) {
      float t0 = bls[g], t1 = t0;
#pragma unroll
      for (int h = 0; h < 16; h++) {
        float w = wls[g * 16 + h];
        t0 += w * sv[h].x; t1 += w * sv[h].y;
      }
      *(float2*)&T[g * 1024 + m] = make_float2(t0, t1);
    }
  }
  __syncthreads();

  // phase 2: softmax per row (warp w -> rows 2w, 2w+1), exp left in T, 1/sum -> invs
  {
    const int g0 = (tid >> 5) * 2;
#pragma unroll
    for (int rr = 0; rr < 2; rr++) {
      float* row = &T[(g0 + rr) << 10];
      float v[32];
#pragma unroll
      for (int j = 0; j < 8; j++) {
        float4 x4 = *(const float4*)&row[lane * 4 + j * 128];
        v[j * 4 + 0] = x4.x; v[j * 4 + 1] = x4.y; v[j * 4 + 2] = x4.z; v[j * 4 + 3] = x4.w;
      }
      float mx = -1e30f;
#pragma unroll
      for (int i = 0; i < 32; i++) mx = fmaxf(mx, v[i]);
#pragma unroll
      for (int o = 16; o; o >>= 1) mx = fmaxf(mx, __shfl_xor_sync(0xffffffffu, mx, o));
      float sum = 0.f;
#pragma unroll
      for (int i = 0; i < 32; i++) { v[i] = __expf(v[i] - mx); sum += v[i]; }
#pragma unroll
      for (int o = 16; o; o >>= 1) sum += __shfl_xor_sync(0xffffffffu, sum, o);
#pragma unroll
      for (int j = 0; j < 8; j++)
        *(float4*)&row[lane * 4 + j * 128] =
            make_float4(v[j * 4 + 0], v[j * 4 + 1], v[j * 4 + 2], v[j * 4 + 3]);
      if (lane == 0) invs[g0 + rr] = 1.0f / sum;
    }
  }
  __syncthreads();
  // fold inv into ww
  wwi[tid] = ww[tid] * invs[tid & 15];
  if (tid < 16) bws[tid] = bw[tid];
  __syncthreads();

  // phase 3: attn[b,g,n,m] = sum_h wwi[g,h] * T[h][m] + bw[g]
  float* ab = attn + (size_t)b * 16 * 1048576 + (size_t)n * 1024;
#pragma unroll
  for (int half = 0; half < 2; half++) {
    const int m = tid * 2 + half * 512;
    float2 ev[16];
#pragma unroll
    for (int h = 0; h < 16; h++) ev[h] = *(const float2*)&T[h * 1024 + m];
#pragma unroll
    for (int g = 0; g < 16; g++) {
      float a0 = bws[g], a1 = a0;
#pragma unroll
      for (int h = 0; h < 16; h++) {
        float w = wwi[g * 16 + h];
        a0 += w * ev[h].x; a1 += w * ev[h].y;
      }
      *(float2*)(ab + (size_t)g * 1048576 + m) = make_float2(a0, a1);
    }
  }
}

// ---------------- launch ----------------
extern "C" void kernel_launch(void* const* d_in, const int* in_sizes, int n_in,
                              void* d_out, int out_size) {
  const float* x      = (const float*)d_in[0];
  const float* qkv_w  = (const float*)d_in[1];
  const float* qkv_b  = (const float*)d_in[2];
  const float* proj_w = (const float*)d_in[3];
  const float* proj_b = (const float*)d_in[4];
  const float* wl     = (const float*)d_in[5];
  const float* bl     = (const float*)d_in[6];
  const float* ww     = (const float*)d_in[7];
  const float* bw     = (const float*)d_in[8];
  float* out = (float*)d_out;
  float* attn = out + (size_t)BB * NN * CC;

  float* scratch = nullptr;
  cudaGetSymbolAddress((void**)&scratch, g_scratch);
  float* q   = scratch + OFF_Q;
  float* k   = scratch + OFF_K;
  float* vT  = scratch + OFF_VT;
  float* mid = scratch + OFF_MID;
  float* s   = scratch + OFF_S;

  static int smem_set = 0;
  const int FUSED_SMEM = (16 * 1024 + 256 + 256 + 16 + 16 + 16) * 4;
  if (!smem_set) {
    cudaFuncSetAttribute(fused_mix_softmax, cudaFuncAttributeMaxDynamicSharedMemorySize, FUSED_SMEM);
    smem_set = 1;
  }

  // 1) qkv = x @ qkv_w^T + b -> q(*0.125), k, vT
  g2_gemm<128, 1><<<dim3(24, 32, 1), 256>>>(
      x, qkv_w, CC, CC, CC, 0, 0, qkv_b, q, k, vT, 0, 0);
  // 2) s[b,h] = q[b,h] @ k[b,h]^T  (64 batches, K=64)
  g2_gemm<128, 0><<<dim3(8, 8, 64), 256>>>(
      q, k, HDIM, HDIM, HDIM, (size_t)NN * HDIM, (size_t)NN * HDIM, nullptr,
      s, nullptr, nullptr, NN, (size_t)NN * NN);
  // 3) fused pre-mix + softmax + post-mix -> final attn
  fused_mix_softmax<<<dim3(NN, BB), 256, FUSED_SMEM>>>(wl, bl, ww, bw, s, attn);
  // 4) mid = attn @ vT^T  (64 batches, K=1024, NT=64)
  g2_gemm<64, 2><<<dim3(1, 8, 64), 256>>>(
      attn, vT, NN, NN, NN, (size_t)NN * NN, (size_t)HDIM * NN, nullptr,
      mid, nullptr, nullptr, 0, 0);
  // 5) out = mid @ proj_w^T + proj_b
  g2_gemm<128, 3><<<dim3(8, 32, 1), 256>>>(
      mid, proj_w, CC, CC, CC, 0, 0, proj_b, out, nullptr, nullptr, CC, 0);
}

// round 5
// speedup vs baseline: 3.2152x; 1.2419x over previous
#include <cuda_runtime.h>
#include <cstdint>

#define BB 4
#define NN 1024
#define CC 1024
#define HH 16
#define HDIM 64

typedef unsigned long long ull;

// ---------------- scratch ----------------
static constexpr size_t OFF_Q   = 0;
static constexpr size_t OFF_K   = OFF_Q + (size_t)BB*HH*NN*HDIM;
static constexpr size_t OFF_VT  = OFF_K + (size_t)BB*HH*NN*HDIM;
static constexpr size_t OFF_MID = OFF_VT + (size_t)BB*HH*NN*HDIM;
static constexpr size_t OFF_S   = OFF_MID + (size_t)BB*NN*CC;
static constexpr size_t SCRATCH_TOTAL = OFF_S + (size_t)BB*HH*NN*NN;
__device__ float g_scratch[SCRATCH_TOTAL];

// ---------------- f32x2 helpers ----------------
__device__ __forceinline__ ull splat2(float v) {
  ull r; asm("mov.b64 %0, {%1,%1};" : "=l"(r) : "f"(v)); return r;
}
__device__ __forceinline__ void fma2(ull& d, ull a, ull b) {
  asm("fma.rn.f32x2 %0, %1, %2, %0;" : "+l"(d) : "l"(a), "l"(b));
}
__device__ __forceinline__ float lo32(ull u) { return __uint_as_float((unsigned)u); }
__device__ __forceinline__ float hi32(ull u) { return __uint_as_float((unsigned)(u >> 32)); }

// ---------------- packed-fp32 GEMM, double-buffered, conflict-free ----------------
// C[128 rows, NT cols] = A[rows,K] @ B[cols,K]^T, fp32, K-major both.
// EPI: 0 plain->O0, 1 qkv scatter, 2 AV->mid, 3 proj+bias->O0
template <int NT, int EPI, int MINB>
__global__ __launch_bounds__(256, MINB) void g2_gemm(
    const float* __restrict__ Ag, const float* __restrict__ Bg,
    int lda, int ldb, int K, size_t batchA, size_t batchB,
    const float* __restrict__ bias,
    float* __restrict__ O0, float* __restrict__ O1, float* __restrict__ O2,
    int ldo, size_t batchO) {
  constexpr int SRA = 132;
  constexpr int SRB = NT + 4;
  constexpr int NCG = NT / 64;       // 4-col groups per thread
  __shared__ float As[2][16 * SRA];
  __shared__ float Bs[2][16 * SRB];

  const int tid = threadIdx.x;
  const int ty = tid >> 4, tx = tid & 15;
  const int row0 = ty * 8;
  const int rb = blockIdx.y * 128, ob = blockIdx.x * NT, z = blockIdx.z;
  const float* Ab = Ag + (size_t)z * batchA;
  const float* Bb = Bg + (size_t)z * batchB;

  ull acc[4][NCG][4];
#pragma unroll
  for (int mp = 0; mp < 4; mp++)
#pragma unroll
    for (int cg = 0; cg < NCG; cg++)
#pragma unroll
      for (int j = 0; j < 4; j++) acc[mp][cg][j] = 0ULL;

  const int ar = tid >> 2, akq = (tid & 3) << 2;  // A load coords (with +64 row step)
  float4 pa[2], pb[NCG];

  auto loadA = [&](int k0) {
#pragma unroll
    for (int i = 0; i < 2; i++)
      pa[i] = __ldg((const float4*)(Ab + (size_t)(rb + ar + i * 64) * lda + k0 + akq));
  };
  auto loadB = [&](int k0) {
#pragma unroll
    for (int i = 0; i < NCG; i++)
      pb[i] = __ldg((const float4*)(Bb + (size_t)(ob + ar + i * 64) * ldb + k0 + akq));
  };
  auto stage = [&](int s) {
#pragma unroll
    for (int i = 0; i < 2; i++) {
      const int r = ar + i * 64;
      As[s][(akq + 0) * SRA + r] = pa[i].x; As[s][(akq + 1) * SRA + r] = pa[i].y;
      As[s][(akq + 2) * SRA + r] = pa[i].z; As[s][(akq + 3) * SRA + r] = pa[i].w;
    }
#pragma unroll
    for (int i = 0; i < NCG; i++) {
      const int r = ar + i * 64;
      Bs[s][(akq + 0) * SRB + r] = pb[i].x; Bs[s][(akq + 1) * SRB + r] = pb[i].y;
      Bs[s][(akq + 2) * SRB + r] = pb[i].z; Bs[s][(akq + 3) * SRB + r] = pb[i].w;
    }
  };

  loadA(0); loadB(0);
  stage(0);
  __syncthreads();

  const int KT = K >> 4;
  int s = 0;
  for (int kt = 0; kt < KT; kt++) {
    if (kt + 1 < KT) { loadA((kt + 1) << 4); loadB((kt + 1) << 4); }
#pragma unroll
    for (int kk = 0; kk < 16; kk++) {
      ulonglong2 a01 = *(const ulonglong2*)&As[s][kk * SRA + row0];
      ulonglong2 a23 = *(const ulonglong2*)&As[s][kk * SRA + row0 + 4];
      ull ap[4] = {a01.x, a01.y, a23.x, a23.y};
#pragma unroll
      for (int cg = 0; cg < NCG; cg++) {
        float4 bf = *(const float4*)&Bs[s][kk * SRB + cg * 64 + tx * 4];
        float bv[4] = {bf.x, bf.y, bf.z, bf.w};
#pragma unroll
        for (int j = 0; j < 4; j++) {
          ull bsp = splat2(bv[j]);
#pragma unroll
          for (int mp = 0; mp < 4; mp++) fma2(acc[mp][cg][j], ap[mp], bsp);
        }
      }
    }
    if (kt + 1 < KT) {
      stage(s ^ 1);
      __syncthreads();
    }
    s ^= 1;
  }

  // ---- epilogue: acc[mp][cg][j] -> rows (rb+row0+2mp, +1), cols ob+cg*64+tx*4+j ----
#pragma unroll
  for (int mp = 0; mp < 4; mp++) {
    const int r0 = rb + row0 + 2 * mp;
#pragma unroll
    for (int cg = 0; cg < NCG; cg++) {
      const int c0 = ob + cg * 64 + tx * 4;
      float lo[4], hi[4];
#pragma unroll
      for (int j = 0; j < 4; j++) { lo[j] = lo32(acc[mp][cg][j]); hi[j] = hi32(acc[mp][cg][j]); }
      if (EPI == 0) {
        float* p0 = O0 + (size_t)z * batchO + (size_t)r0 * ldo + c0;
        *(float4*)p0 = make_float4(lo[0], lo[1], lo[2], lo[3]);
        *(float4*)(p0 + ldo) = make_float4(hi[0], hi[1], hi[2], hi[3]);
      } else if (EPI == 1) {
        const int which = c0 >> 10, h = (c0 >> 6) & 15, d0 = c0 & 63;
        const int bcb = r0 >> 10, n0 = r0 & 1023;
        float4 bi = __ldg((const float4*)(bias + c0));
        float bv[4] = {bi.x, bi.y, bi.z, bi.w};
        if (which == 2) {
#pragma unroll
          for (int j = 0; j < 4; j++)
            *(float2*)(O2 + ((((size_t)bcb * HH + h) * HDIM + d0 + j) << 10) + n0) =
                make_float2(lo[j] + bv[j], hi[j] + bv[j]);
        } else {
          float* dst = (which == 0) ? O0 : O1;
          const float sc = (which == 0) ? 0.125f : 1.0f;
          float* p0 = dst + (((size_t)bcb * HH + h) * NN + n0) * HDIM + d0;
          *(float4*)p0 = make_float4((lo[0] + bv[0]) * sc, (lo[1] + bv[1]) * sc,
                                     (lo[2] + bv[2]) * sc, (lo[3] + bv[3]) * sc);
          *(float4*)(p0 + HDIM) = make_float4((hi[0] + bv[0]) * sc, (hi[1] + bv[1]) * sc,
                                              (hi[2] + bv[2]) * sc, (hi[3] + bv[3]) * sc);
        }
      } else if (EPI == 2) {
        const int bcb = z >> 4, g = z & 15;
        float* p0 = O0 + ((size_t)bcb * NN + r0) * CC + g * HDIM + c0;
        *(float4*)p0 = make_float4(lo[0], lo[1], lo[2], lo[3]);
        *(float4*)(p0 + CC) = make_float4(hi[0], hi[1], hi[2], hi[3]);
      } else {
        float4 bi = __ldg((const float4*)(bias + c0));
        float* p0 = O0 + (size_t)r0 * ldo + c0;
        *(float4*)p0 = make_float4(lo[0] + bi.x, lo[1] + bi.y, lo[2] + bi.z, lo[3] + bi.w);
        *(float4*)(p0 + ldo) = make_float4(hi[0] + bi.x, hi[1] + bi.y, hi[2] + bi.z, hi[3] + bi.w);
      }
    }
  }
}

// ---------------- fused mix1 + softmax + mix2 (FMA2) ----------------
// CTA per (n, b). Thread owns 4 m-columns. T[16][1024] in smem.
__global__ __launch_bounds__(256) void fused_mix_softmax(
    const float* __restrict__ wl, const float* __restrict__ bl,
    const float* __restrict__ ww, const float* __restrict__ bw,
    const float* __restrict__ s, float* __restrict__ attn) {
  extern __shared__ float sm[];
  float* T = sm;                     // 16*1024
  float* wls  = sm + 16 * 1024;      // 256
  float* wwi  = wls + 256;           // 256
  float* bls  = wwi + 256;           // 16
  float* bws  = bls + 16;            // 16
  float* invs = bws + 16;            // 16
  const int n = blockIdx.x, b = blockIdx.y, tid = threadIdx.x;
  const int lane = tid & 31;
  wls[tid] = wl[tid];
  if (tid < 16) bls[tid] = bl[tid];
  __syncthreads();

  // phase 1: T[g][m0..m0+3] = sum_h wl[g,h]*s[b,h,n,m] + bl[g]
  const float* sb = s + (((size_t)b * 16) << 20) + ((size_t)n << 10) + tid * 4;
  {
    ull sv[16][2];
#pragma unroll
    for (int h = 0; h < 16; h++) {
      float4 v = __ldg((const float4*)(sb + ((size_t)h << 20)));
      sv[h][0] = splat2(0.f); sv[h][1] = splat2(0.f);
      asm("mov.b64 %0, {%1,%2};" : "=l"(sv[h][0]) : "f"(v.x), "f"(v.y));
      asm("mov.b64 %0, {%1,%2};" : "=l"(sv[h][1]) : "f"(v.z), "f"(v.w));
    }
#pragma unroll
    for (int g = 0; g < 16; g++) {
      ull a0 = splat2(bls[g]), a1 = a0;
#pragma unroll
      for (int h = 0; h < 16; h++) {
        ull wsp = splat2(wls[g * 16 + h]);
        fma2(a0, wsp, sv[h][0]);
        fma2(a1, wsp, sv[h][1]);
      }
      *(float4*)&T[g * 1024 + tid * 4] = make_float4(lo32(a0), hi32(a0), lo32(a1), hi32(a1));
    }
  }
  __syncthreads();

  // phase 2: softmax rows (warp w -> rows 2w, 2w+1); exp left in T, 1/sum -> invs
  {
    const int g0 = (tid >> 5) * 2;
#pragma unroll
    for (int rr = 0; rr < 2; rr++) {
      float* row = &T[(g0 + rr) << 10];
      float v[32];
#pragma unroll
      for (int j = 0; j < 8; j++) {
        float4 x4 = *(const float4*)&row[lane * 4 + j * 128];
        v[j * 4 + 0] = x4.x; v[j * 4 + 1] = x4.y; v[j * 4 + 2] = x4.z; v[j * 4 + 3] = x4.w;
      }
      float mx = -1e30f;
#pragma unroll
      for (int i = 0; i < 32; i++) mx = fmaxf(mx, v[i]);
#pragma unroll
      for (int o = 16; o; o >>= 1) mx = fmaxf(mx, __shfl_xor_sync(0xffffffffu, mx, o));
      float sum = 0.f;
#pragma unroll
      for (int i = 0; i < 32; i++) { v[i] = __expf(v[i] - mx); sum += v[i]; }
#pragma unroll
      for (int o = 16; o; o >>= 1) sum += __shfl_xor_sync(0xffffffffu, sum, o);
#pragma unroll
      for (int j = 0; j < 8; j++)
        *(float4*)&row[lane * 4 + j * 128] =
            make_float4(v[j * 4 + 0], v[j * 4 + 1], v[j * 4 + 2], v[j * 4 + 3]);
      if (lane == 0) invs[g0 + rr] = 1.0f / sum;
    }
  }
  __syncthreads();
  wwi[tid] = ww[tid] * invs[tid & 15];
  if (tid < 16) bws[tid] = bw[tid];
  __syncthreads();

  // phase 3: attn = ww*(exp/sum) + bw
  float* ab = attn + (((size_t)b * 16) << 20) + ((size_t)n << 10) + tid * 4;
  {
    ull ev[16][2];
#pragma unroll
    for (int h = 0; h < 16; h++) {
      ulonglong2 u = *(const ulonglong2*)&T[h * 1024 + tid * 4];
      ev[h][0] = u.x; ev[h][1] = u.y;
    }
#pragma unroll
    for (int g = 0; g < 16; g++) {
      ull a0 = splat2(bws[g]), a1 = a0;
#pragma unroll
      for (int h = 0; h < 16; h++) {
        ull wsp = splat2(wwi[g * 16 + h]);
        fma2(a0, wsp, ev[h][0]);
        fma2(a1, wsp, ev[h][1]);
      }
      *(float4*)(ab + ((size_t)g << 20)) = make_float4(lo32(a0), hi32(a0), lo32(a1), hi32(a1));
    }
  }
}

// ---------------- launch ----------------
extern "C" void kernel_launch(void* const* d_in, const int* in_sizes, int n_in,
                              void* d_out, int out_size) {
  const float* x      = (const float*)d_in[0];
  const float* qkv_w  = (const float*)d_in[1];
  const float* qkv_b  = (const float*)d_in[2];
  const float* proj_w = (const float*)d_in[3];
  const float* proj_b = (const float*)d_in[4];
  const float* wl     = (const float*)d_in[5];
  const float* bl     = (const float*)d_in[6];
  const float* ww     = (const float*)d_in[7];
  const float* bw     = (const float*)d_in[8];
  float* out = (float*)d_out;
  float* attn = out + (size_t)BB * NN * CC;

  float* scratch = nullptr;
  cudaGetSymbolAddress((void**)&scratch, g_scratch);
  float* q   = scratch + OFF_Q;
  float* k   = scratch + OFF_K;
  float* vT  = scratch + OFF_VT;
  float* mid = scratch + OFF_MID;
  float* s   = scratch + OFF_S;

  static int smem_set = 0;
  const int FUSED_SMEM = (16 * 1024 + 256 + 256 + 16 + 16 + 16) * 4;
  if (!smem_set) {
    cudaFuncSetAttribute(fused_mix_softmax, cudaFuncAttributeMaxDynamicSharedMemorySize, FUSED_SMEM);
    smem_set = 1;
  }

  // 1) qkv = x @ qkv_w^T + b -> q(*0.125), k, vT
  g2_gemm<128, 1, 2><<<dim3(24, 32, 1), 256>>>(
      x, qkv_w, CC, CC, CC, 0, 0, qkv_b, q, k, vT, 0, 0);
  // 2) s[b,h] = q[b,h] @ k[b,h]^T  (64 batches, K=64)
  g2_gemm<128, 0, 2><<<dim3(8, 8, 64), 256>>>(
      q, k, HDIM, HDIM, HDIM, (size_t)NN * HDIM, (size_t)NN * HDIM, nullptr,
      s, nullptr, nullptr, NN, (size_t)NN * NN);
  // 3) fused pre-mix + softmax + post-mix -> final attn
  fused_mix_softmax<<<dim3(NN, BB), 256, FUSED_SMEM>>>(wl, bl, ww, bw, s, attn);
  // 4) mid = attn @ vT^T  (64 batches, K=1024, NT=64)
  g2_gemm<64, 2, 3><<<dim3(1, 8, 64), 256>>>(
      attn, vT, NN, NN, NN, (size_t)NN * NN, (size_t)HDIM * NN, nullptr,
      mid, nullptr, nullptr, 0, 0);
  // 5) out = mid @ proj_w^T + proj_b
  g2_gemm<128, 3, 2><<<dim3(8, 32, 1), 256>>>(
      mid, proj_w, CC, CC, CC, 0, 0, proj_b, out, nullptr, nullptr, CC, 0);
}